// round 1
// baseline (speedup 1.0000x reference)
#include <cuda_runtime.h>
#include <math.h>

#define BSZ   32768
#define IND   256
#define NFEAT 8
#define EDIM  16
#define VOCAB 100000
#define DNUM  4

// ------------------------- scratch (device globals; no allocs) ----------
__device__ float g_gate_in[(size_t)BSZ * IND];               //  34 MB
__device__ float g_h0[(size_t)DNUM * BSZ * 256];             // 134 MB
__device__ float g_h1[(size_t)DNUM * BSZ * 256];             // 134 MB
__device__ float g_g1[(size_t)DNUM * BSZ * 256];             // 134 MB
__device__ float g_gt[(size_t)DNUM * BSZ * 256];             // 134 MB
__device__ float g_sums[2 * DNUM * 256];
__device__ float g_scale[DNUM * 256];
__device__ float g_shift[DNUM * 256];

// ------------------------- embedding gather -----------------------------
// gate_in[b, f*16+e]       = id_tables[f, id_idx[b,f], e]
// gate_in[b, 128 + f*16+e] = agn_tables[f, agn_idx[b,f], e]
__global__ void embed_kernel(const int* __restrict__ id_idx,
                             const int* __restrict__ agn_idx,
                             const float* __restrict__ id_tab,
                             const float* __restrict__ agn_tab) {
    int t = blockIdx.x * blockDim.x + threadIdx.x;   // BSZ*64 threads, 4 floats each
    if (t >= BSZ * 64) return;
    int b = t >> 6;
    int j = (t & 63) << 2;                           // 0..252, step 4
    const int*   idx = id_idx;
    const float* tab = id_tab;
    int jj = j;
    if (j >= 128) { idx = agn_idx; tab = agn_tab; jj = j - 128; }
    int f = jj >> 4, e = jj & 15;
    int v = idx[b * NFEAT + f];
    float4 val = *(const float4*)(tab + ((size_t)f * VOCAB + v) * EDIM + e);
    *(float4*)(g_gate_in + (size_t)b * IND + j) = val;
}

// ------------------------- GEMM: C[d] = A[d] (BSZ x K) @ W[d] (K x N) + bias[d]
// EPI: 0 = none, 1 = relu, 2 = 2*sigmoid
// 64x64 block tile, BK=16, 256 threads, 4x4 per-thread micro tile.
template <int EPI>
__global__ void gemm_kernel(const float* __restrict__ A, size_t aDomStride,
                            const float* __restrict__ W,
                            const float* __restrict__ bias,
                            float* __restrict__ C,
                            int K, int N) {
    const int BK = 16;
    int d  = blockIdx.z;
    int bm = blockIdx.x * 64;
    int bn = blockIdx.y * 64;
    const float* Ad = A + (size_t)d * aDomStride;
    const float* Wd = W + (size_t)d * K * N;
    float*       Cd = C + ((size_t)d * BSZ + bm) * N + bn;

    __shared__ float As[BK][64];
    __shared__ float Bs[BK][64];

    int tid = threadIdx.x;              // 0..255
    int tx = tid & 15, ty = tid >> 4;   // 16 x 16
    int arow = tid >> 2, ak = (tid & 3) << 2;     // A tile load: 64 rows x 16 k
    int bk   = tid >> 4, bn4 = (tid & 15) << 2;   // W tile load: 16 k   x 64 n

    const float* Aptr = Ad + (size_t)(bm + arow) * K + ak;
    const float* Wptr = Wd + (size_t)bk * N + bn + bn4;

    float acc[4][4] = {};

    for (int k0 = 0; k0 < K; k0 += BK) {
        float4 a4 = *(const float4*)(Aptr + k0);
        As[ak + 0][arow] = a4.x;
        As[ak + 1][arow] = a4.y;
        As[ak + 2][arow] = a4.z;
        As[ak + 3][arow] = a4.w;
        *(float4*)&Bs[bk][bn4] = *(const float4*)(Wptr + (size_t)k0 * N);
        __syncthreads();
#pragma unroll
        for (int kk = 0; kk < BK; kk++) {
            float a0 = As[kk][ty * 4 + 0];
            float a1 = As[kk][ty * 4 + 1];
            float a2 = As[kk][ty * 4 + 2];
            float a3 = As[kk][ty * 4 + 3];
            float b0 = Bs[kk][tx * 4 + 0];
            float b1 = Bs[kk][tx * 4 + 1];
            float b2 = Bs[kk][tx * 4 + 2];
            float b3 = Bs[kk][tx * 4 + 3];
            acc[0][0] += a0 * b0; acc[0][1] += a0 * b1; acc[0][2] += a0 * b2; acc[0][3] += a0 * b3;
            acc[1][0] += a1 * b0; acc[1][1] += a1 * b1; acc[1][2] += a1 * b2; acc[1][3] += a1 * b3;
            acc[2][0] += a2 * b0; acc[2][1] += a2 * b1; acc[2][2] += a2 * b2; acc[2][3] += a2 * b3;
            acc[3][0] += a3 * b0; acc[3][1] += a3 * b1; acc[3][2] += a3 * b2; acc[3][3] += a3 * b3;
        }
        __syncthreads();
    }

#pragma unroll
    for (int i = 0; i < 4; i++) {
#pragma unroll
        for (int j = 0; j < 4; j++) {
            float v = acc[i][j] + bias[d * N + bn + tx * 4 + j];
            if (EPI == 1) v = fmaxf(v, 0.0f);
            if (EPI == 2) v = 2.0f / (1.0f + expf(-v));
            Cd[(size_t)(ty * 4 + i) * N + tx * 4 + j] = v;
        }
    }
}

// ------------------------- BatchNorm -----------------------------------
__global__ void zero_stats() {
    int t = blockIdx.x * blockDim.x + threadIdx.x;
    if (t < 2 * DNUM * 256) g_sums[t] = 0.0f;
}

// grid (256, DNUM), block 256: each block reduces 128 rows x N channels.
__global__ void bn_stats(const float* __restrict__ H, int N) {
    const int ROWS = BSZ / 256;          // 128
    int d   = blockIdx.y;
    int tid = threadIdx.x;
    int c     = tid % N;
    int rsub  = tid / N;
    int rstep = 256 / N;
    const float* Hd = H + (size_t)d * BSZ * N + (size_t)blockIdx.x * ROWS * N;
    float s = 0.0f, q = 0.0f;
    for (int r = rsub; r < ROWS; r += rstep) {
        float v = Hd[(size_t)r * N + c];
        s += v;
        q += v * v;
    }
    atomicAdd(&g_sums[d * 256 + c], s);
    atomicAdd(&g_sums[DNUM * 256 + d * 256 + c], q);
}

__global__ void bn_finalize(const float* __restrict__ bng,
                            const float* __restrict__ bnb, int N) {
    int t = blockIdx.x * blockDim.x + threadIdx.x;
    if (t >= DNUM * N) return;
    int d = t / N, c = t % N;
    float mean = g_sums[d * 256 + c] * (1.0f / BSZ);
    float var  = g_sums[DNUM * 256 + d * 256 + c] * (1.0f / BSZ) - mean * mean;
    float sc   = bng[d * N + c] * rsqrtf(var + 1e-5f);
    g_scale[d * N + c] = sc;
    g_shift[d * N + c] = bnb[d * N + c] - mean * sc;
}

// h = relu(h_pre*scale + shift) * gate   (in place on H)
__global__ void bn_apply_gate(float* __restrict__ H, const float* __restrict__ G, int N) {
    size_t t = (size_t)blockIdx.x * blockDim.x + threadIdx.x;
    size_t total4 = (size_t)DNUM * BSZ * N / 4;
    if (t >= total4) return;
    size_t e = t * 4;
    int c = (int)(e % N);
    int d = (int)(e / ((size_t)BSZ * N));
    int base = d * N + c;
    float4 h = *(float4*)(H + e);
    float4 g = *(const float4*)(G + e);
    h.x = fmaxf(h.x * g_scale[base + 0] + g_shift[base + 0], 0.0f) * g.x;
    h.y = fmaxf(h.y * g_scale[base + 1] + g_shift[base + 1], 0.0f) * g.y;
    h.z = fmaxf(h.z * g_scale[base + 2] + g_shift[base + 2], 0.0f) * g.z;
    h.w = fmaxf(h.w * g_scale[base + 3] + g_shift[base + 3], 0.0f) * g.w;
    *(float4*)(H + e) = h;
}

// ------------------------- final head ----------------------------------
// out[b] = sigmoid( dot(h[dom[b], b, :64], finW[dom[b]]) + finb[dom[b]] )
__global__ void final_kernel(const float* __restrict__ H,
                             const int* __restrict__ dom,
                             const float* __restrict__ finW,
                             const float* __restrict__ finb,
                             float* __restrict__ out) {
    int warp = (blockIdx.x * blockDim.x + threadIdx.x) >> 5;
    int lane = threadIdx.x & 31;
    if (warp >= BSZ) return;
    int d = dom[warp];
    const float* h = H + ((size_t)d * BSZ + warp) * 64;
    const float* w = finW + d * 64;
    float s = h[lane] * w[lane] + h[lane + 32] * w[lane + 32];
#pragma unroll
    for (int o = 16; o > 0; o >>= 1) s += __shfl_down_sync(0xffffffffu, s, o);
    if (lane == 0) out[warp] = 1.0f / (1.0f + expf(-(s + finb[d])));
}

// ------------------------- launch --------------------------------------
extern "C" void kernel_launch(void* const* d_in, const int* in_sizes, int n_in,
                              void* d_out, int out_size) {
    const int*   id_idx    = (const int*)d_in[0];
    const int*   agn_idx   = (const int*)d_in[1];
    const int*   domain_id = (const int*)d_in[2];
    const float* id_tab    = (const float*)d_in[3];
    const float* agn_tab   = (const float*)d_in[4];
    const float* mlp_W[3]  = {(const float*)d_in[5],  (const float*)d_in[13], (const float*)d_in[21]};
    const float* mlp_b[3]  = {(const float*)d_in[6],  (const float*)d_in[14], (const float*)d_in[22]};
    const float* bn_g[3]   = {(const float*)d_in[7],  (const float*)d_in[15], (const float*)d_in[23]};
    const float* bn_b[3]   = {(const float*)d_in[8],  (const float*)d_in[16], (const float*)d_in[24]};
    const float* gW1[3]    = {(const float*)d_in[9],  (const float*)d_in[17], (const float*)d_in[25]};
    const float* gb1[3]    = {(const float*)d_in[10], (const float*)d_in[18], (const float*)d_in[26]};
    const float* gW2[3]    = {(const float*)d_in[11], (const float*)d_in[19], (const float*)d_in[27]};
    const float* gb2[3]    = {(const float*)d_in[12], (const float*)d_in[20], (const float*)d_in[28]};
    const float* finW      = (const float*)d_in[29];
    const float* finb      = (const float*)d_in[30];
    float*       out       = (float*)d_out;

    float *p_gate_in, *p_h0, *p_h1, *p_g1, *p_gt;
    cudaGetSymbolAddress((void**)&p_gate_in, g_gate_in);
    cudaGetSymbolAddress((void**)&p_h0, g_h0);
    cudaGetSymbolAddress((void**)&p_h1, g_h1);
    cudaGetSymbolAddress((void**)&p_g1, g_g1);
    cudaGetSymbolAddress((void**)&p_gt, g_gt);

    embed_kernel<<<(BSZ * 64 + 255) / 256, 256>>>(id_idx, agn_idx, id_tab, agn_tab);

    const int dims[4] = {256, 256, 128, 64};   // DIMS
    float* hbuf[2] = {p_h0, p_h1};
    const float* hprev = nullptr;

    for (int i = 0; i < 3; i++) {
        int Kmlp = dims[i];
        int N    = dims[i + 1];
        float* hout = hbuf[i & 1];   // L0->h0, L1->h1, L2->h0 (reads h1, no alias)

        dim3 grid(BSZ / 64, N / 64, DNUM);

        // g1 = relu(gate_in @ gW1 + gb1)       [K = 256]
        gemm_kernel<1><<<grid, 256>>>(p_gate_in, 0, gW1[i], gb1[i], p_g1, IND, N);
        // gate = 2*sigmoid(g1 @ gW2 + gb2)     [K = N]
        gemm_kernel<2><<<grid, 256>>>(p_g1, (size_t)BSZ * N, gW2[i], gb2[i], p_gt, N, N);
        // h_pre = X @ mlp_W + mlp_b
        if (i == 0)
            gemm_kernel<0><<<grid, 256>>>(p_gate_in, 0, mlp_W[i], mlp_b[i], hout, IND, N);
        else
            gemm_kernel<0><<<grid, 256>>>(hprev, (size_t)BSZ * Kmlp, mlp_W[i], mlp_b[i], hout, Kmlp, N);

        zero_stats<<<8, 256>>>();
        dim3 sgrid(256, DNUM);
        bn_stats<<<sgrid, 256>>>(hout, N);
        bn_finalize<<<4, 256>>>(bn_g[i], bn_b[i], N);

        size_t tot4 = (size_t)DNUM * BSZ * N / 4;
        bn_apply_gate<<<(unsigned)((tot4 + 255) / 256), 256>>>(hout, p_gt, N);

        hprev = hout;
    }

    final_kernel<<<BSZ / 8, 256>>>(hprev, domain_id, finW, finb, out);
}

// round 2
// speedup vs baseline: 1.1747x; 1.1747x over previous
#include <cuda_runtime.h>
#include <math.h>

#define BSZ   32768
#define IND   256
#define NFEAT 8
#define EDIM  16
#define VOCAB 100000
#define DNUM  4

// ------------------------- scratch (device globals; no allocs) ----------
__device__ float g_gate_in[(size_t)BSZ * IND];               //  34 MB
__device__ float g_h0[(size_t)DNUM * BSZ * 256];             // 134 MB
__device__ float g_h1[(size_t)DNUM * BSZ * 256];             // 134 MB
__device__ float g_g1[(size_t)DNUM * BSZ * 256];             // 134 MB
__device__ float g_gt[(size_t)DNUM * BSZ * 256];             // 134 MB
__device__ float g_sums[2 * DNUM * 256];
__device__ float g_scale[DNUM * 256];
__device__ float g_shift[DNUM * 256];

// ------------------------- embedding gather -----------------------------
__global__ void embed_kernel(const int* __restrict__ id_idx,
                             const int* __restrict__ agn_idx,
                             const float* __restrict__ id_tab,
                             const float* __restrict__ agn_tab) {
    int t = blockIdx.x * blockDim.x + threadIdx.x;   // BSZ*64 threads, 4 floats each
    if (t >= BSZ * 64) return;
    int b = t >> 6;
    int j = (t & 63) << 2;                           // 0..252, step 4
    const int*   idx = id_idx;
    const float* tab = id_tab;
    int jj = j;
    if (j >= 128) { idx = agn_idx; tab = agn_tab; jj = j - 128; }
    int f = jj >> 4, e = jj & 15;
    int v = idx[b * NFEAT + f];
    float4 val = *(const float4*)(tab + ((size_t)f * VOCAB + v) * EDIM + e);
    *(float4*)(g_gate_in + (size_t)b * IND + j) = val;
}

// ------------------------- GEMM -----------------------------------------
// C[d] = A[d] (BSZ x K) @ W[d] (K x N) + bias[d];  EPI: 0 none, 1 relu, 2 2*sigmoid
// BM=128, BN in {128,64}, BK=16. 256 threads = 16(n) x 16(m). Microtile 8 x TN.
template <int BN, int EPI>
__global__ void __launch_bounds__(256, 2)
gemm_kernel(const float* __restrict__ A, size_t aDomStride,
            const float* __restrict__ W,
            const float* __restrict__ bias,
            float* __restrict__ C,
            int K, int N) {
    constexpr int BM = 128, BK = 16, TM = 8;
    constexpr int TN = BN / 16;          // 8 or 4

    int d  = blockIdx.z;
    int bm = blockIdx.x * BM;
    int bn = blockIdx.y * BN;
    const float* Ad = A + (size_t)d * aDomStride + (size_t)bm * K;
    const float* Wd = W + (size_t)d * K * N + bn;
    float*       Cd = C + ((size_t)d * BSZ + bm) * N + bn;

    __shared__ float As[BK][BM];
    __shared__ float Bs[BK][BN];

    int tid = threadIdx.x;
    int tx  = tid & 15;                  // n-group
    int ty  = tid >> 4;                  // m-group

    // A tile load: 128 rows x 16 k. float4 along k. 2 rows per thread.
    int arow = tid >> 2;                 // 0..63
    int akc  = (tid & 3) << 2;           // 0,4,8,12
    // B tile load: 16 rows x BN. float4 along n.
    int bkr  = tid >> 4;                 // 0..15
    int bnc  = (tid & 15) << 2;          // 0..60

    const float* Aptr0 = Ad + (size_t)arow * K + akc;
    const float* Aptr1 = Ad + (size_t)(arow + 64) * K + akc;
    const float* Bptr  = Wd + (size_t)bkr * N + bnc;

    float acc[TM][TN] = {};
    float4 pa0, pa1, pb0, pb1;

    pa0 = *(const float4*)(Aptr0);
    pa1 = *(const float4*)(Aptr1);
    pb0 = *(const float4*)(Bptr);
    if (BN == 128) pb1 = *(const float4*)(Bptr + 64);

    for (int k0 = 0; k0 < K; k0 += BK) {
        // store staged tile
        As[akc + 0][arow] = pa0.x;  As[akc + 1][arow] = pa0.y;
        As[akc + 2][arow] = pa0.z;  As[akc + 3][arow] = pa0.w;
        As[akc + 0][arow + 64] = pa1.x;  As[akc + 1][arow + 64] = pa1.y;
        As[akc + 2][arow + 64] = pa1.z;  As[akc + 3][arow + 64] = pa1.w;
        *(float4*)&Bs[bkr][bnc] = pb0;
        if (BN == 128) *(float4*)&Bs[bkr][bnc + 64] = pb1;
        __syncthreads();

        // prefetch next tile into registers
        if (k0 + BK < K) {
            pa0 = *(const float4*)(Aptr0 + k0 + BK);
            pa1 = *(const float4*)(Aptr1 + k0 + BK);
            pb0 = *(const float4*)(Bptr + (size_t)(k0 + BK) * N);
            if (BN == 128) pb1 = *(const float4*)(Bptr + (size_t)(k0 + BK) * N + 64);
        }

#pragma unroll
        for (int kk = 0; kk < BK; kk++) {
            float a[TM], b[TN];
            *(float4*)&a[0] = *(const float4*)&As[kk][ty * TM];
            *(float4*)&a[4] = *(const float4*)&As[kk][ty * TM + 4];
            *(float4*)&b[0] = *(const float4*)&Bs[kk][tx * TN];
            if (TN == 8) *(float4*)&b[4] = *(const float4*)&Bs[kk][tx * TN + 4];
#pragma unroll
            for (int i = 0; i < TM; i++)
#pragma unroll
                for (int j = 0; j < TN; j++)
                    acc[i][j] += a[i] * b[j];
        }
        __syncthreads();
    }

    // epilogue
    float bb[TN];
#pragma unroll
    for (int j = 0; j < TN; j++) bb[j] = bias[d * N + bn + tx * TN + j];

#pragma unroll
    for (int i = 0; i < TM; i++) {
        float v[TN];
#pragma unroll
        for (int j = 0; j < TN; j++) {
            float x = acc[i][j] + bb[j];
            if (EPI == 1) x = fmaxf(x, 0.0f);
            if (EPI == 2) x = 2.0f / (1.0f + expf(-x));
            v[j] = x;
        }
        float* crow = Cd + (size_t)(ty * TM + i) * N + tx * TN;
        *(float4*)crow = *(float4*)&v[0];
        if (TN == 8) *(float4*)(crow + 4) = *(float4*)&v[4];
    }
}

// ------------------------- BatchNorm -----------------------------------
__global__ void zero_stats() {
    int t = blockIdx.x * blockDim.x + threadIdx.x;
    if (t < 2 * DNUM * 256) g_sums[t] = 0.0f;
}

__global__ void bn_stats(const float* __restrict__ H, int N) {
    const int ROWS = BSZ / 256;          // 128
    int d   = blockIdx.y;
    int tid = threadIdx.x;
    int c     = tid % N;
    int rsub  = tid / N;
    int rstep = 256 / N;
    const float* Hd = H + (size_t)d * BSZ * N + (size_t)blockIdx.x * ROWS * N;
    float s = 0.0f, q = 0.0f;
    for (int r = rsub; r < ROWS; r += rstep) {
        float v = Hd[(size_t)r * N + c];
        s += v;
        q += v * v;
    }
    atomicAdd(&g_sums[d * 256 + c], s);
    atomicAdd(&g_sums[DNUM * 256 + d * 256 + c], q);
}

__global__ void bn_finalize(const float* __restrict__ bng,
                            const float* __restrict__ bnb, int N) {
    int t = blockIdx.x * blockDim.x + threadIdx.x;
    if (t >= DNUM * N) return;
    int d = t / N, c = t % N;
    float mean = g_sums[d * 256 + c] * (1.0f / BSZ);
    float var  = g_sums[DNUM * 256 + d * 256 + c] * (1.0f / BSZ) - mean * mean;
    float sc   = bng[d * N + c] * rsqrtf(var + 1e-5f);
    g_scale[d * N + c] = sc;
    g_shift[d * N + c] = bnb[d * N + c] - mean * sc;
}

__global__ void bn_apply_gate(float* __restrict__ H, const float* __restrict__ G, int N) {
    size_t t = (size_t)blockIdx.x * blockDim.x + threadIdx.x;
    size_t total4 = (size_t)DNUM * BSZ * N / 4;
    if (t >= total4) return;
    size_t e = t * 4;
    int c = (int)(e % N);
    int d = (int)(e / ((size_t)BSZ * N));
    int base = d * N + c;
    float4 h = *(float4*)(H + e);
    float4 g = *(const float4*)(G + e);
    h.x = fmaxf(h.x * g_scale[base + 0] + g_shift[base + 0], 0.0f) * g.x;
    h.y = fmaxf(h.y * g_scale[base + 1] + g_shift[base + 1], 0.0f) * g.y;
    h.z = fmaxf(h.z * g_scale[base + 2] + g_shift[base + 2], 0.0f) * g.z;
    h.w = fmaxf(h.w * g_scale[base + 3] + g_shift[base + 3], 0.0f) * g.w;
    *(float4*)(H + e) = h;
}

// ------------------------- final head ----------------------------------
__global__ void final_kernel(const float* __restrict__ H,
                             const int* __restrict__ dom,
                             const float* __restrict__ finW,
                             const float* __restrict__ finb,
                             float* __restrict__ out) {
    int warp = (blockIdx.x * blockDim.x + threadIdx.x) >> 5;
    int lane = threadIdx.x & 31;
    if (warp >= BSZ) return;
    int d = dom[warp];
    const float* h = H + ((size_t)d * BSZ + warp) * 64;
    const float* w = finW + d * 64;
    float s = h[lane] * w[lane] + h[lane + 32] * w[lane + 32];
#pragma unroll
    for (int o = 16; o > 0; o >>= 1) s += __shfl_down_sync(0xffffffffu, s, o);
    if (lane == 0) out[warp] = 1.0f / (1.0f + expf(-(s + finb[d])));
}

// ------------------------- dispatch helper ------------------------------
template <int EPI>
static void launch_gemm(const float* A, size_t aStride, const float* W,
                        const float* b, float* C, int K, int N) {
    if (N >= 128) {
        dim3 grid(BSZ / 128, N / 128, DNUM);
        gemm_kernel<128, EPI><<<grid, 256>>>(A, aStride, W, b, C, K, N);
    } else {
        dim3 grid(BSZ / 128, N / 64, DNUM);
        gemm_kernel<64, EPI><<<grid, 256>>>(A, aStride, W, b, C, K, N);
    }
}

// ------------------------- launch --------------------------------------
extern "C" void kernel_launch(void* const* d_in, const int* in_sizes, int n_in,
                              void* d_out, int out_size) {
    const int*   id_idx    = (const int*)d_in[0];
    const int*   agn_idx   = (const int*)d_in[1];
    const int*   domain_id = (const int*)d_in[2];
    const float* id_tab    = (const float*)d_in[3];
    const float* agn_tab   = (const float*)d_in[4];
    const float* mlp_W[3]  = {(const float*)d_in[5],  (const float*)d_in[13], (const float*)d_in[21]};
    const float* mlp_b[3]  = {(const float*)d_in[6],  (const float*)d_in[14], (const float*)d_in[22]};
    const float* bn_g[3]   = {(const float*)d_in[7],  (const float*)d_in[15], (const float*)d_in[23]};
    const float* bn_b[3]   = {(const float*)d_in[8],  (const float*)d_in[16], (const float*)d_in[24]};
    const float* gW1[3]    = {(const float*)d_in[9],  (const float*)d_in[17], (const float*)d_in[25]};
    const float* gb1[3]    = {(const float*)d_in[10], (const float*)d_in[18], (const float*)d_in[26]};
    const float* gW2[3]    = {(const float*)d_in[11], (const float*)d_in[19], (const float*)d_in[27]};
    const float* gb2[3]    = {(const float*)d_in[12], (const float*)d_in[20], (const float*)d_in[28]};
    const float* finW      = (const float*)d_in[29];
    const float* finb      = (const float*)d_in[30];
    float*       out       = (float*)d_out;

    float *p_gate_in, *p_h0, *p_h1, *p_g1, *p_gt;
    cudaGetSymbolAddress((void**)&p_gate_in, g_gate_in);
    cudaGetSymbolAddress((void**)&p_h0, g_h0);
    cudaGetSymbolAddress((void**)&p_h1, g_h1);
    cudaGetSymbolAddress((void**)&p_g1, g_g1);
    cudaGetSymbolAddress((void**)&p_gt, g_gt);

    embed_kernel<<<(BSZ * 64 + 255) / 256, 256>>>(id_idx, agn_idx, id_tab, agn_tab);

    const int dims[4] = {256, 256, 128, 64};   // DIMS
    float* hbuf[2] = {p_h0, p_h1};
    const float* hprev = nullptr;

    for (int i = 0; i < 3; i++) {
        int Kmlp = dims[i];
        int N    = dims[i + 1];
        float* hout = hbuf[i & 1];   // L0->h0, L1->h1, L2->h0 (reads h1, no alias)

        // g1 = relu(gate_in @ gW1 + gb1)       [K = 256]
        launch_gemm<1>(p_gate_in, 0, gW1[i], gb1[i], p_g1, IND, N);
        // gate = 2*sigmoid(g1 @ gW2 + gb2)     [K = N]
        launch_gemm<2>(p_g1, (size_t)BSZ * N, gW2[i], gb2[i], p_gt, N, N);
        // h_pre = X @ mlp_W + mlp_b
        if (i == 0)
            launch_gemm<0>(p_gate_in, 0, mlp_W[i], mlp_b[i], hout, IND, N);
        else
            launch_gemm<0>(hprev, (size_t)BSZ * Kmlp, mlp_W[i], mlp_b[i], hout, Kmlp, N);

        zero_stats<<<8, 256>>>();
        dim3 sgrid(256, DNUM);
        bn_stats<<<sgrid, 256>>>(hout, N);
        bn_finalize<<<4, 256>>>(bn_g[i], bn_b[i], N);

        size_t tot4 = (size_t)DNUM * BSZ * N / 4;
        bn_apply_gate<<<(unsigned)((tot4 + 255) / 256), 256>>>(hout, p_gt, N);

        hprev = hout;
    }

    final_kernel<<<BSZ / 8, 256>>>(hprev, domain_id, finW, finb, out);
}

// round 3
// speedup vs baseline: 2.5822x; 2.1983x over previous
#include <cuda_runtime.h>
#include <math.h>

#define BSZ   32768
#define IND   256
#define NFEAT 8
#define EDIM  16
#define VOCAB 100000
#define DNUM  4

// ------------------------- scratch (device globals; no allocs) ----------
__device__ float g_gate_in[(size_t)BSZ * IND];
__device__ float g_h0[(size_t)DNUM * BSZ * 256];
__device__ float g_h1[(size_t)DNUM * BSZ * 256];
__device__ float g_g1[(size_t)DNUM * BSZ * 256];
__device__ float g_gt[(size_t)DNUM * BSZ * 256];
__device__ float g_sums[2 * DNUM * 256];
__device__ float g_scale[DNUM * 256];
__device__ float g_shift[DNUM * 256];

// ------------------------- helpers --------------------------------------
__device__ __forceinline__ unsigned f2tf32(float x) {
    unsigned r;
    asm("cvt.rna.tf32.f32 %0, %1;" : "=r"(r) : "f"(x));
    return r;
}

__device__ __forceinline__ void mma_tf32(float c[4], const unsigned a[4], const unsigned b[2]) {
    asm volatile(
        "mma.sync.aligned.m16n8k8.row.col.f32.tf32.tf32.f32 "
        "{%0,%1,%2,%3}, {%4,%5,%6,%7}, {%8,%9}, {%0,%1,%2,%3};"
        : "+f"(c[0]), "+f"(c[1]), "+f"(c[2]), "+f"(c[3])
        : "r"(a[0]), "r"(a[1]), "r"(a[2]), "r"(a[3]), "r"(b[0]), "r"(b[1]));
}

// ------------------------- embedding gather -----------------------------
__global__ void embed_kernel(const int* __restrict__ id_idx,
                             const int* __restrict__ agn_idx,
                             const float* __restrict__ id_tab,
                             const float* __restrict__ agn_tab) {
    int t = blockIdx.x * blockDim.x + threadIdx.x;
    if (t >= BSZ * 64) return;
    int b = t >> 6;
    int j = (t & 63) << 2;
    const int*   idx = id_idx;
    const float* tab = id_tab;
    int jj = j;
    if (j >= 128) { idx = agn_idx; tab = agn_tab; jj = j - 128; }
    int f = jj >> 4, e = jj & 15;
    int v = idx[b * NFEAT + f];
    float4 val = *(const float4*)(tab + ((size_t)f * VOCAB + v) * EDIM + e);
    *(float4*)(g_gate_in + (size_t)b * IND + j) = val;
}

// ------------------------- tensor-core GEMM ------------------------------
// C[d] = A[d] (BSZ x K) @ W[d] (K x N) + bias[d];  EPI: 0 none, 1 relu, 2 2*sigmoid
// BM=128, BK=16. 8 warps: 4 (m) x 2 (n). Warp tile 32 x (BN/2). mma m16n8k8 tf32.
template <int BN, int EPI>
__global__ void __launch_bounds__(256, 2)
gemm_tc(const float* __restrict__ A, size_t aDomStride,
        const float* __restrict__ W,
        const float* __restrict__ bias,
        float* __restrict__ C,
        int K, int N) {
    constexpr int BM = 128, BK = 16;
    constexpr int WN = BN / 2;           // 64 or 32
    constexpr int NI = WN / 8;           // 8 or 4
    constexpr int APAD = 20;             // floats per A row (16 + 4) -> conflict-free frags
    constexpr int BPAD = BN + 8;         // floats per B row -> conflict-free frags

    __shared__ unsigned As[BM][APAD];
    __shared__ unsigned Bs[BK][BPAD];

    int d  = blockIdx.z;
    int bm = blockIdx.x * BM;
    int bn = blockIdx.y * BN;
    const float* Ad = A + (size_t)d * aDomStride + (size_t)bm * K;
    const float* Wd = W + (size_t)d * K * N + bn;
    float*       Cd = C + ((size_t)d * BSZ + bm) * N + bn;

    int tid  = threadIdx.x;
    int lane = tid & 31, wid = tid >> 5;
    int gid  = lane >> 2, tig = lane & 3;
    int wm   = wid >> 1,  wn  = wid & 1;

    // staging indices
    int arow = tid >> 2, akc = (tid & 3) << 2;     // A: 64 rows x 16k (x2 row groups)
    int bkr  = tid >> 4, bnc = (tid & 15) << 2;    // B: 16 rows x BN

    const float* Aptr0 = Ad + (size_t)arow * K + akc;
    const float* Aptr1 = Ad + (size_t)(arow + 64) * K + akc;
    const float* Bptr  = Wd + (size_t)bkr * N + bnc;

    float acc[2][NI][4] = {};

    float4 pa0 = *(const float4*)(Aptr0);
    float4 pa1 = *(const float4*)(Aptr1);
    float4 pb0 = *(const float4*)(Bptr);
    float4 pb1;
    if (BN == 128) pb1 = *(const float4*)(Bptr + 64);

    for (int k0 = 0; k0 < K; k0 += BK) {
        As[arow][akc + 0] = f2tf32(pa0.x);
        As[arow][akc + 1] = f2tf32(pa0.y);
        As[arow][akc + 2] = f2tf32(pa0.z);
        As[arow][akc + 3] = f2tf32(pa0.w);
        As[arow + 64][akc + 0] = f2tf32(pa1.x);
        As[arow + 64][akc + 1] = f2tf32(pa1.y);
        As[arow + 64][akc + 2] = f2tf32(pa1.z);
        As[arow + 64][akc + 3] = f2tf32(pa1.w);
        Bs[bkr][bnc + 0] = f2tf32(pb0.x);
        Bs[bkr][bnc + 1] = f2tf32(pb0.y);
        Bs[bkr][bnc + 2] = f2tf32(pb0.z);
        Bs[bkr][bnc + 3] = f2tf32(pb0.w);
        if (BN == 128) {
            Bs[bkr][bnc + 64] = f2tf32(pb1.x);
            Bs[bkr][bnc + 65] = f2tf32(pb1.y);
            Bs[bkr][bnc + 66] = f2tf32(pb1.z);
            Bs[bkr][bnc + 67] = f2tf32(pb1.w);
        }
        __syncthreads();

        if (k0 + BK < K) {
            pa0 = *(const float4*)(Aptr0 + k0 + BK);
            pa1 = *(const float4*)(Aptr1 + k0 + BK);
            pb0 = *(const float4*)(Bptr + (size_t)(k0 + BK) * N);
            if (BN == 128) pb1 = *(const float4*)(Bptr + (size_t)(k0 + BK) * N + 64);
        }

#pragma unroll
        for (int ks = 0; ks < 2; ks++) {
            int kk = ks * 8;
            unsigned af[2][4], bf[NI][2];
#pragma unroll
            for (int mi = 0; mi < 2; mi++) {
                int r0 = wm * 32 + mi * 16 + gid;
                af[mi][0] = As[r0][kk + tig];
                af[mi][1] = As[r0 + 8][kk + tig];
                af[mi][2] = As[r0][kk + tig + 4];
                af[mi][3] = As[r0 + 8][kk + tig + 4];
            }
#pragma unroll
            for (int ni = 0; ni < NI; ni++) {
                int cb = wn * WN + ni * 8 + gid;
                bf[ni][0] = Bs[kk + tig][cb];
                bf[ni][1] = Bs[kk + tig + 4][cb];
            }
#pragma unroll
            for (int mi = 0; mi < 2; mi++)
#pragma unroll
                for (int ni = 0; ni < NI; ni++)
                    mma_tf32(acc[mi][ni], af[mi], bf[ni]);
        }
        __syncthreads();
    }

    // epilogue: c0,c1 at (gid, 2tig..2tig+1), c2,c3 at (gid+8, ...)
#pragma unroll
    for (int mi = 0; mi < 2; mi++) {
        int r0 = wm * 32 + mi * 16 + gid;
#pragma unroll
        for (int ni = 0; ni < NI; ni++) {
            int col = wn * WN + ni * 8 + 2 * tig;
            float b0 = bias[d * N + bn + col];
            float b1 = bias[d * N + bn + col + 1];
            float v0 = acc[mi][ni][0] + b0;
            float v1 = acc[mi][ni][1] + b1;
            float v2 = acc[mi][ni][2] + b0;
            float v3 = acc[mi][ni][3] + b1;
            if (EPI == 1) {
                v0 = fmaxf(v0, 0.0f); v1 = fmaxf(v1, 0.0f);
                v2 = fmaxf(v2, 0.0f); v3 = fmaxf(v3, 0.0f);
            }
            if (EPI == 2) {
                v0 = 2.0f / (1.0f + expf(-v0)); v1 = 2.0f / (1.0f + expf(-v1));
                v2 = 2.0f / (1.0f + expf(-v2)); v3 = 2.0f / (1.0f + expf(-v3));
            }
            *(float2*)(Cd + (size_t)r0 * N + col)       = make_float2(v0, v1);
            *(float2*)(Cd + (size_t)(r0 + 8) * N + col) = make_float2(v2, v3);
        }
    }
}

// ------------------------- BatchNorm -----------------------------------
__global__ void zero_stats() {
    int t = blockIdx.x * blockDim.x + threadIdx.x;
    if (t < 2 * DNUM * 256) g_sums[t] = 0.0f;
}

__global__ void bn_stats(const float* __restrict__ H, int N) {
    const int ROWS = BSZ / 256;
    int d   = blockIdx.y;
    int tid = threadIdx.x;
    int c     = tid % N;
    int rsub  = tid / N;
    int rstep = 256 / N;
    const float* Hd = H + (size_t)d * BSZ * N + (size_t)blockIdx.x * ROWS * N;
    float s = 0.0f, q = 0.0f;
    for (int r = rsub; r < ROWS; r += rstep) {
        float v = Hd[(size_t)r * N + c];
        s += v;
        q += v * v;
    }
    atomicAdd(&g_sums[d * 256 + c], s);
    atomicAdd(&g_sums[DNUM * 256 + d * 256 + c], q);
}

__global__ void bn_finalize(const float* __restrict__ bng,
                            const float* __restrict__ bnb, int N) {
    int t = blockIdx.x * blockDim.x + threadIdx.x;
    if (t >= DNUM * N) return;
    int d = t / N, c = t % N;
    float mean = g_sums[d * 256 + c] * (1.0f / BSZ);
    float var  = g_sums[DNUM * 256 + d * 256 + c] * (1.0f / BSZ) - mean * mean;
    float sc   = bng[d * N + c] * rsqrtf(var + 1e-5f);
    g_scale[d * N + c] = sc;
    g_shift[d * N + c] = bnb[d * N + c] - mean * sc;
}

__global__ void bn_apply_gate(float* __restrict__ H, const float* __restrict__ G, int N) {
    size_t t = (size_t)blockIdx.x * blockDim.x + threadIdx.x;
    size_t total4 = (size_t)DNUM * BSZ * N / 4;
    if (t >= total4) return;
    size_t e = t * 4;
    int c = (int)(e % N);
    int d = (int)(e / ((size_t)BSZ * N));
    int base = d * N + c;
    float4 h = *(float4*)(H + e);
    float4 g = *(const float4*)(G + e);
    h.x = fmaxf(h.x * g_scale[base + 0] + g_shift[base + 0], 0.0f) * g.x;
    h.y = fmaxf(h.y * g_scale[base + 1] + g_shift[base + 1], 0.0f) * g.y;
    h.z = fmaxf(h.z * g_scale[base + 2] + g_shift[base + 2], 0.0f) * g.z;
    h.w = fmaxf(h.w * g_scale[base + 3] + g_shift[base + 3], 0.0f) * g.w;
    *(float4*)(H + e) = h;
}

// ------------------------- final head ----------------------------------
__global__ void final_kernel(const float* __restrict__ H,
                             const int* __restrict__ dom,
                             const float* __restrict__ finW,
                             const float* __restrict__ finb,
                             float* __restrict__ out) {
    int warp = (blockIdx.x * blockDim.x + threadIdx.x) >> 5;
    int lane = threadIdx.x & 31;
    if (warp >= BSZ) return;
    int d = dom[warp];
    const float* h = H + ((size_t)d * BSZ + warp) * 64;
    const float* w = finW + d * 64;
    float s = h[lane] * w[lane] + h[lane + 32] * w[lane + 32];
#pragma unroll
    for (int o = 16; o > 0; o >>= 1) s += __shfl_down_sync(0xffffffffu, s, o);
    if (lane == 0) out[warp] = 1.0f / (1.0f + expf(-(s + finb[d])));
}

// ------------------------- dispatch helper ------------------------------
template <int EPI>
static void launch_gemm(const float* A, size_t aStride, const float* W,
                        const float* b, float* C, int K, int N) {
    if (N >= 128) {
        dim3 grid(BSZ / 128, N / 128, DNUM);
        gemm_tc<128, EPI><<<grid, 256>>>(A, aStride, W, b, C, K, N);
    } else {
        dim3 grid(BSZ / 128, N / 64, DNUM);
        gemm_tc<64, EPI><<<grid, 256>>>(A, aStride, W, b, C, K, N);
    }
}

// ------------------------- launch --------------------------------------
extern "C" void kernel_launch(void* const* d_in, const int* in_sizes, int n_in,
                              void* d_out, int out_size) {
    const int*   id_idx    = (const int*)d_in[0];
    const int*   agn_idx   = (const int*)d_in[1];
    const int*   domain_id = (const int*)d_in[2];
    const float* id_tab    = (const float*)d_in[3];
    const float* agn_tab   = (const float*)d_in[4];
    const float* mlp_W[3]  = {(const float*)d_in[5],  (const float*)d_in[13], (const float*)d_in[21]};
    const float* mlp_b[3]  = {(const float*)d_in[6],  (const float*)d_in[14], (const float*)d_in[22]};
    const float* bn_g[3]   = {(const float*)d_in[7],  (const float*)d_in[15], (const float*)d_in[23]};
    const float* bn_b[3]   = {(const float*)d_in[8],  (const float*)d_in[16], (const float*)d_in[24]};
    const float* gW1[3]    = {(const float*)d_in[9],  (const float*)d_in[17], (const float*)d_in[25]};
    const float* gb1[3]    = {(const float*)d_in[10], (const float*)d_in[18], (const float*)d_in[26]};
    const float* gW2[3]    = {(const float*)d_in[11], (const float*)d_in[19], (const float*)d_in[27]};
    const float* gb2[3]    = {(const float*)d_in[12], (const float*)d_in[20], (const float*)d_in[28]};
    const float* finW      = (const float*)d_in[29];
    const float* finb      = (const float*)d_in[30];
    float*       out       = (float*)d_out;

    float *p_gate_in, *p_h0, *p_h1, *p_g1, *p_gt;
    cudaGetSymbolAddress((void**)&p_gate_in, g_gate_in);
    cudaGetSymbolAddress((void**)&p_h0, g_h0);
    cudaGetSymbolAddress((void**)&p_h1, g_h1);
    cudaGetSymbolAddress((void**)&p_g1, g_g1);
    cudaGetSymbolAddress((void**)&p_gt, g_gt);

    embed_kernel<<<(BSZ * 64 + 255) / 256, 256>>>(id_idx, agn_idx, id_tab, agn_tab);

    const int dims[4] = {256, 256, 128, 64};
    float* hbuf[2] = {p_h0, p_h1};
    const float* hprev = nullptr;

    for (int i = 0; i < 3; i++) {
        int Kmlp = dims[i];
        int N    = dims[i + 1];
        float* hout = hbuf[i & 1];

        launch_gemm<1>(p_gate_in, 0, gW1[i], gb1[i], p_g1, IND, N);
        launch_gemm<2>(p_g1, (size_t)BSZ * N, gW2[i], gb2[i], p_gt, N, N);
        if (i == 0)
            launch_gemm<0>(p_gate_in, 0, mlp_W[i], mlp_b[i], hout, IND, N);
        else
            launch_gemm<0>(hprev, (size_t)BSZ * Kmlp, mlp_W[i], mlp_b[i], hout, Kmlp, N);

        zero_stats<<<8, 256>>>();
        dim3 sgrid(256, DNUM);
        bn_stats<<<sgrid, 256>>>(hout, N);
        bn_finalize<<<4, 256>>>(bn_g[i], bn_b[i], N);

        size_t tot4 = (size_t)DNUM * BSZ * N / 4;
        bn_apply_gate<<<(unsigned)((tot4 + 255) / 256), 256>>>(hout, p_gt, N);

        hprev = hout;
    }

    final_kernel<<<BSZ / 8, 256>>>(hprev, domain_id, finW, finb, out);
}

// round 4
// speedup vs baseline: 2.7652x; 1.0709x over previous
#include <cuda_runtime.h>
#include <math.h>
#include <stdint.h>

#define BSZ   32768
#define IND   256
#define NFEAT 8
#define EDIM  16
#define VOCAB 100000
#define DNUM  4

// ------------------------- scratch (device globals; no allocs) ----------
__device__ float g_gate_in[(size_t)BSZ * IND];
__device__ float g_h0[(size_t)DNUM * BSZ * 256];
__device__ float g_h1[(size_t)DNUM * BSZ * 256];
__device__ float g_g1[(size_t)DNUM * BSZ * 256];
__device__ float g_gt[(size_t)DNUM * BSZ * 256];
__device__ float g_sums3[3][2 * DNUM * 256];          // per-layer [s|q][d][c]
__device__ float g_wrnd[1300000];                      // rounded weights (~5MB)

// ------------------------- helpers --------------------------------------
__device__ __forceinline__ unsigned f2tf32(float x) {
    unsigned r;
    asm("cvt.rna.tf32.f32 %0, %1;" : "=r"(r) : "f"(x));
    return r;
}
__device__ __forceinline__ float roundtf(float x) { return __uint_as_float(f2tf32(x)); }

__device__ __forceinline__ void mma_tf32(float c[4], const unsigned a[4], const unsigned b[2]) {
    asm volatile(
        "mma.sync.aligned.m16n8k8.row.col.f32.tf32.tf32.f32 "
        "{%0,%1,%2,%3}, {%4,%5,%6,%7}, {%8,%9}, {%0,%1,%2,%3};"
        : "+f"(c[0]), "+f"(c[1]), "+f"(c[2]), "+f"(c[3])
        : "r"(a[0]), "r"(a[1]), "r"(a[2]), "r"(a[3]), "r"(b[0]), "r"(b[1]));
}

__device__ __forceinline__ void cp16(uint32_t dst, const float* src) {
    asm volatile("cp.async.cg.shared.global [%0], [%1], 16;" :: "r"(dst), "l"(src));
}
#define CP_COMMIT() asm volatile("cp.async.commit_group;")
#define CP_WAIT0()  asm volatile("cp.async.wait_group 0;")

// ------------------------- weight rounding ------------------------------
struct RoundSeg { const float* src; float* dst; int n; };
struct RoundArgs { RoundSeg seg[9]; };
__global__ void round_weights(RoundArgs a) {
    int s = blockIdx.y;
    int i = blockIdx.x * 256 + threadIdx.x;
    if (i < a.seg[s].n) a.seg[s].dst[i] = roundtf(a.seg[s].src[i]);
}

// ------------------------- embedding gather (+ zero sums) ---------------
__global__ void embed_kernel(const int* __restrict__ id_idx,
                             const int* __restrict__ agn_idx,
                             const float* __restrict__ id_tab,
                             const float* __restrict__ agn_tab) {
    int t = blockIdx.x * blockDim.x + threadIdx.x;
    if (t < 3 * 2 * DNUM * 256) ((float*)g_sums3)[t] = 0.0f;
    if (t >= BSZ * 64) return;
    int b = t >> 6;
    int j = (t & 63) << 2;
    const int*   idx = id_idx;
    const float* tab = id_tab;
    int jj = j;
    if (j >= 128) { idx = agn_idx; tab = agn_tab; jj = j - 128; }
    int f = jj >> 4, e = jj & 15;
    int v = idx[b * NFEAT + f];
    float4 val = *(const float4*)(tab + ((size_t)f * VOCAB + v) * EDIM + e);
    val.x = roundtf(val.x); val.y = roundtf(val.y);
    val.z = roundtf(val.z); val.w = roundtf(val.w);
    *(float4*)(g_gate_in + (size_t)b * IND + j) = val;
}

// ------------------------- tensor-core GEMM ------------------------------
// C[d] = A[d] (BSZ x K) @ W[d] (K x N) + bias[d]
// EPI: 0 = none + column stats (mlp pre-BN), 1 = relu + tf32 round, 2 = 2*sigmoid
// A and W MUST be pre-rounded to tf32. BM=128, BK=16, 2-stage cp.async pipeline.
template <int BN, int EPI>
__global__ void __launch_bounds__(256, 2)
gemm_tc(const float* __restrict__ A, size_t aDomStride,
        const float* __restrict__ W,
        const float* __restrict__ bias,
        float* __restrict__ C,
        float* __restrict__ sums,
        int K, int N) {
    constexpr int BM = 128, BK = 16;
    constexpr int WN = BN / 2;
    constexpr int NI = WN / 8;
    constexpr int APAD = 20;
    constexpr int BPAD = BN + 8;

    __shared__ __align__(16) float As[2][BM][APAD];
    __shared__ __align__(16) float Bs[2][BK][BPAD];
    __shared__ float cs[BN], cq[BN];

    int d  = blockIdx.z;
    int bm = blockIdx.x * BM;
    int bn = blockIdx.y * BN;
    const float* Ad = A + (size_t)d * aDomStride + (size_t)bm * K;
    const float* Wd = W + (size_t)d * K * N + bn;
    float*       Cd = C + ((size_t)d * BSZ + bm) * N + bn;

    int tid  = threadIdx.x;
    int lane = tid & 31, wid = tid >> 5;
    int gid  = lane >> 2, tig = lane & 3;
    int wm   = wid >> 1,  wn  = wid & 1;

    int arow = tid >> 2, akc = (tid & 3) << 2;     // A: 64 rows x 16k, two row groups
    int bkr  = tid >> 4, bnc = (tid & 15) << 2;    // B: 16 rows x BN (x2 col groups if 128)

    const float* Aptr0 = Ad + (size_t)arow * K + akc;
    const float* Aptr1 = Ad + (size_t)(arow + 64) * K + akc;
    const float* Bptr  = Wd + (size_t)bkr * N + bnc;

    uint32_t sA = (uint32_t)__cvta_generic_to_shared(&As[0][0][0]);
    uint32_t sB = (uint32_t)__cvta_generic_to_shared(&Bs[0][0][0]);

    float acc[2][NI][4] = {};

    // prologue: stage 0
    cp16(sA + (((0 * BM + arow) * APAD + akc) << 2), Aptr0);
    cp16(sA + (((0 * BM + arow + 64) * APAD + akc) << 2), Aptr1);
    cp16(sB + (((0 * BK + bkr) * BPAD + bnc) << 2), Bptr);
    if (BN == 128) cp16(sB + (((0 * BK + bkr) * BPAD + bnc + 64) << 2), Bptr + 64);
    CP_COMMIT();

    int s = 0;
    for (int k0 = 0; k0 < K; k0 += BK) {
        CP_WAIT0();
        __syncthreads();

        if (k0 + BK < K) {
            int ns = s ^ 1;
            cp16(sA + (((ns * BM + arow) * APAD + akc) << 2), Aptr0 + k0 + BK);
            cp16(sA + (((ns * BM + arow + 64) * APAD + akc) << 2), Aptr1 + k0 + BK);
            cp16(sB + (((ns * BK + bkr) * BPAD + bnc) << 2), Bptr + (size_t)(k0 + BK) * N);
            if (BN == 128)
                cp16(sB + (((ns * BK + bkr) * BPAD + bnc + 64) << 2), Bptr + (size_t)(k0 + BK) * N + 64);
            CP_COMMIT();
        }

#pragma unroll
        for (int ks = 0; ks < 2; ks++) {
            int kk = ks * 8;
            unsigned af[2][4], bf[NI][2];
#pragma unroll
            for (int mi = 0; mi < 2; mi++) {
                int r0 = wm * 32 + mi * 16 + gid;
                af[mi][0] = __float_as_uint(As[s][r0][kk + tig]);
                af[mi][1] = __float_as_uint(As[s][r0 + 8][kk + tig]);
                af[mi][2] = __float_as_uint(As[s][r0][kk + tig + 4]);
                af[mi][3] = __float_as_uint(As[s][r0 + 8][kk + tig + 4]);
            }
#pragma unroll
            for (int ni = 0; ni < NI; ni++) {
                int cb = wn * WN + ni * 8 + gid;
                bf[ni][0] = __float_as_uint(Bs[s][kk + tig][cb]);
                bf[ni][1] = __float_as_uint(Bs[s][kk + tig + 4][cb]);
            }
#pragma unroll
            for (int mi = 0; mi < 2; mi++)
#pragma unroll
                for (int ni = 0; ni < NI; ni++)
                    mma_tf32(acc[mi][ni], af[mi], bf[ni]);
        }
        s ^= 1;
    }

    if (EPI == 0) {
        if (tid < BN) { cs[tid] = 0.0f; cq[tid] = 0.0f; }
        __syncthreads();
    }

    float colS[NI][2] = {}, colQ[NI][2] = {};

#pragma unroll
    for (int mi = 0; mi < 2; mi++) {
        int r0 = wm * 32 + mi * 16 + gid;
#pragma unroll
        for (int ni = 0; ni < NI; ni++) {
            int col = wn * WN + ni * 8 + 2 * tig;
            float b0 = bias[d * N + bn + col];
            float b1 = bias[d * N + bn + col + 1];
            float v0 = acc[mi][ni][0] + b0;
            float v1 = acc[mi][ni][1] + b1;
            float v2 = acc[mi][ni][2] + b0;
            float v3 = acc[mi][ni][3] + b1;
            if (EPI == 1) {
                v0 = roundtf(fmaxf(v0, 0.0f)); v1 = roundtf(fmaxf(v1, 0.0f));
                v2 = roundtf(fmaxf(v2, 0.0f)); v3 = roundtf(fmaxf(v3, 0.0f));
            }
            if (EPI == 2) {
                v0 = 2.0f / (1.0f + expf(-v0)); v1 = 2.0f / (1.0f + expf(-v1));
                v2 = 2.0f / (1.0f + expf(-v2)); v3 = 2.0f / (1.0f + expf(-v3));
            }
            if (EPI == 0) {
                colS[ni][0] += v0 + v2;      colS[ni][1] += v1 + v3;
                colQ[ni][0] += v0 * v0 + v2 * v2;
                colQ[ni][1] += v1 * v1 + v3 * v3;
            }
            *(float2*)(Cd + (size_t)r0 * N + col)       = make_float2(v0, v1);
            *(float2*)(Cd + (size_t)(r0 + 8) * N + col) = make_float2(v2, v3);
        }
    }

    if (EPI == 0) {
#pragma unroll
        for (int ni = 0; ni < NI; ni++)
#pragma unroll
            for (int c2 = 0; c2 < 2; c2++) {
                float sv = colS[ni][c2], qv = colQ[ni][c2];
                sv += __shfl_xor_sync(0xffffffffu, sv, 16);
                sv += __shfl_xor_sync(0xffffffffu, sv, 8);
                sv += __shfl_xor_sync(0xffffffffu, sv, 4);
                qv += __shfl_xor_sync(0xffffffffu, qv, 16);
                qv += __shfl_xor_sync(0xffffffffu, qv, 8);
                qv += __shfl_xor_sync(0xffffffffu, qv, 4);
                if (gid == 0) {
                    int c = wn * WN + ni * 8 + 2 * tig + c2;
                    atomicAdd(&cs[c], sv);
                    atomicAdd(&cq[c], qv);
                }
            }
        __syncthreads();
        if (tid < BN) {
            atomicAdd(&sums[d * 256 + bn + tid], cs[tid]);
            atomicAdd(&sums[DNUM * 256 + d * 256 + bn + tid], cq[tid]);
        }
    }
}

// ------------------------- BN apply + gate (finalize folded in) ---------
// h = round_tf32( relu(h_pre*scale + shift) * gate )
__global__ void bn_apply_gate(float* __restrict__ H, const float* __restrict__ G,
                              const float* __restrict__ sums,
                              const float* __restrict__ bng,
                              const float* __restrict__ bnb, int N) {
    size_t t = (size_t)blockIdx.x * blockDim.x + threadIdx.x;
    size_t total4 = (size_t)DNUM * BSZ * N / 4;
    if (t >= total4) return;
    size_t e = t * 4;
    int c = (int)(e % N);
    int d = (int)(e / ((size_t)BSZ * N));
    float4 h = *(float4*)(H + e);
    float4 g = *(const float4*)(G + e);
    float r[4] = {h.x, h.y, h.z, h.w};
    float gg[4] = {g.x, g.y, g.z, g.w};
#pragma unroll
    for (int j = 0; j < 4; j++) {
        int idx = d * 256 + c + j;          // sums layout uses 256 stride
        float mean = sums[idx] * (1.0f / BSZ);
        float var  = sums[DNUM * 256 + idx] * (1.0f / BSZ) - mean * mean;
        float sc   = bng[d * N + c + j] * rsqrtf(var + 1e-5f);
        float sh   = bnb[d * N + c + j] - mean * sc;
        r[j] = roundtf(fmaxf(r[j] * sc + sh, 0.0f) * gg[j]);
    }
    *(float4*)(H + e) = make_float4(r[0], r[1], r[2], r[3]);
}

// ------------------------- final head ----------------------------------
__global__ void final_kernel(const float* __restrict__ H,
                             const int* __restrict__ dom,
                             const float* __restrict__ finW,
                             const float* __restrict__ finb,
                             float* __restrict__ out) {
    int warp = (blockIdx.x * blockDim.x + threadIdx.x) >> 5;
    int lane = threadIdx.x & 31;
    if (warp >= BSZ) return;
    int d = dom[warp];
    const float* h = H + ((size_t)d * BSZ + warp) * 64;
    const float* w = finW + d * 64;
    float s = h[lane] * w[lane] + h[lane + 32] * w[lane + 32];
#pragma unroll
    for (int o = 16; o > 0; o >>= 1) s += __shfl_down_sync(0xffffffffu, s, o);
    if (lane == 0) out[warp] = 1.0f / (1.0f + expf(-(s + finb[d])));
}

// ------------------------- dispatch helper ------------------------------
template <int EPI>
static void launch_gemm(const float* A, size_t aStride, const float* W,
                        const float* b, float* C, float* sums, int K, int N) {
    if (N >= 128) {
        dim3 grid(BSZ / 128, N / 128, DNUM);
        gemm_tc<128, EPI><<<grid, 256>>>(A, aStride, W, b, C, sums, K, N);
    } else {
        dim3 grid(BSZ / 128, N / 64, DNUM);
        gemm_tc<64, EPI><<<grid, 256>>>(A, aStride, W, b, C, sums, K, N);
    }
}

// ------------------------- launch --------------------------------------
extern "C" void kernel_launch(void* const* d_in, const int* in_sizes, int n_in,
                              void* d_out, int out_size) {
    const int*   id_idx    = (const int*)d_in[0];
    const int*   agn_idx   = (const int*)d_in[1];
    const int*   domain_id = (const int*)d_in[2];
    const float* id_tab    = (const float*)d_in[3];
    const float* agn_tab   = (const float*)d_in[4];
    const float* mlp_W[3]  = {(const float*)d_in[5],  (const float*)d_in[13], (const float*)d_in[21]};
    const float* mlp_b[3]  = {(const float*)d_in[6],  (const float*)d_in[14], (const float*)d_in[22]};
    const float* bn_g[3]   = {(const float*)d_in[7],  (const float*)d_in[15], (const float*)d_in[23]};
    const float* bn_b[3]   = {(const float*)d_in[8],  (const float*)d_in[16], (const float*)d_in[24]};
    const float* gW1[3]    = {(const float*)d_in[9],  (const float*)d_in[17], (const float*)d_in[25]};
    const float* gb1[3]    = {(const float*)d_in[10], (const float*)d_in[18], (const float*)d_in[26]};
    const float* gW2[3]    = {(const float*)d_in[11], (const float*)d_in[19], (const float*)d_in[27]};
    const float* gb2[3]    = {(const float*)d_in[12], (const float*)d_in[20], (const float*)d_in[28]};
    const float* finW      = (const float*)d_in[29];
    const float* finb      = (const float*)d_in[30];
    float*       out       = (float*)d_out;

    float *p_gate_in, *p_h0, *p_h1, *p_g1, *p_gt, *p_sums, *p_w;
    cudaGetSymbolAddress((void**)&p_gate_in, g_gate_in);
    cudaGetSymbolAddress((void**)&p_h0, g_h0);
    cudaGetSymbolAddress((void**)&p_h1, g_h1);
    cudaGetSymbolAddress((void**)&p_g1, g_g1);
    cudaGetSymbolAddress((void**)&p_gt, g_gt);
    cudaGetSymbolAddress((void**)&p_sums, g_sums3);
    cudaGetSymbolAddress((void**)&p_w, g_wrnd);

    const int dims[4] = {256, 256, 128, 64};

    // rounded-weight scratch layout
    float* rW1[3]; float* rW2[3]; float* rWm[3];
    size_t off = 0;
    RoundArgs ra;
    int segi = 0, maxn = 0;
    for (int i = 0; i < 3; i++) {
        int N = dims[i + 1];
        rW1[i] = p_w + off;
        ra.seg[segi++] = {gW1[i], p_w + off, DNUM * IND * N};      off += (size_t)DNUM * IND * N;
        rW2[i] = p_w + off;
        ra.seg[segi++] = {gW2[i], p_w + off, DNUM * N * N};        off += (size_t)DNUM * N * N;
        rWm[i] = p_w + off;
        ra.seg[segi++] = {mlp_W[i], p_w + off, DNUM * dims[i] * N}; off += (size_t)DNUM * dims[i] * N;
    }
    for (int s = 0; s < 9; s++) if (ra.seg[s].n > maxn) maxn = ra.seg[s].n;

    dim3 rg((maxn + 255) / 256, 9);
    round_weights<<<rg, 256>>>(ra);

    embed_kernel<<<(BSZ * 64 + 255) / 256, 256>>>(id_idx, agn_idx, id_tab, agn_tab);

    float* hbuf[2] = {p_h0, p_h1};
    const float* hprev = nullptr;

    for (int i = 0; i < 3; i++) {
        int Kmlp = dims[i];
        int N    = dims[i + 1];
        float* hout = hbuf[i & 1];
        float* sums = p_sums + (size_t)i * 2 * DNUM * 256;

        launch_gemm<1>(p_gate_in, 0, rW1[i], gb1[i], p_g1, nullptr, IND, N);
        launch_gemm<2>(p_g1, (size_t)BSZ * N, rW2[i], gb2[i], p_gt, nullptr, N, N);
        if (i == 0)
            launch_gemm<0>(p_gate_in, 0, rWm[i], mlp_b[i], hout, sums, IND, N);
        else
            launch_gemm<0>(hprev, (size_t)BSZ * Kmlp, rWm[i], mlp_b[i], hout, sums, Kmlp, N);

        size_t tot4 = (size_t)DNUM * BSZ * N / 4;
        bn_apply_gate<<<(unsigned)((tot4 + 255) / 256), 256>>>(hout, p_gt, sums, bn_g[i], bn_b[i], N);

        hprev = hout;
    }

    final_kernel<<<BSZ / 8, 256>>>(hprev, domain_id, finW, finb, out);
}

// round 6
// speedup vs baseline: 2.9269x; 1.0585x over previous
#include <cuda_runtime.h>
#include <math.h>
#include <stdint.h>

#define BSZ   32768
#define IND   256
#define NFEAT 8
#define EDIM  16
#define VOCAB 100000
#define DNUM  4

// ------------------------- scratch (device globals; no allocs) ----------
__device__ float g_gate_in[(size_t)BSZ * IND];
__device__ float g_h0[(size_t)DNUM * BSZ * 256];
__device__ float g_h1[(size_t)DNUM * BSZ * 256];
__device__ float g_g1[(size_t)DNUM * BSZ * 256];
__device__ float g_gt[(size_t)DNUM * BSZ * 256];
__device__ float g_sums3[3][2 * DNUM * 256];
__device__ float g_wrnd[1300000];                 // packed tf32 weights

// ------------------------- helpers --------------------------------------
__device__ __forceinline__ unsigned f2tf32(float x) {
    unsigned r;
    asm("cvt.rna.tf32.f32 %0, %1;" : "=r"(r) : "f"(x));
    return r;
}
__device__ __forceinline__ float roundtf(float x) { return __uint_as_float(f2tf32(x)); }

__device__ __forceinline__ void mma_tf32(float c[4], const unsigned a[4], const unsigned b[2]) {
    asm volatile(
        "mma.sync.aligned.m16n8k8.row.col.f32.tf32.tf32.f32 "
        "{%0,%1,%2,%3}, {%4,%5,%6,%7}, {%8,%9}, {%0,%1,%2,%3};"
        : "+f"(c[0]), "+f"(c[1]), "+f"(c[2]), "+f"(c[3])
        : "r"(a[0]), "r"(a[1]), "r"(a[2]), "r"(a[3]), "r"(b[0]), "r"(b[1]));
}

__device__ __forceinline__ void cp16(uint32_t dst, const float* src) {
    asm volatile("cp.async.cg.shared.global [%0], [%1], 16;" :: "r"(dst), "l"(src));
}
#define CP_COMMIT() asm volatile("cp.async.commit_group;" ::: "memory")
#define CP_WAIT0()  asm volatile("cp.async.wait_group 0;" ::: "memory")

// ------------------------- weight prep: round + fragment-pack -----------
// src: W[d][k][n] row-major.
// dst: P[d][kt][n][tig] = float4{ w(16kt+tig+0,n), w(+4,n), w(+8,n), w(+12,n) }
//      (float index: ((d*(K/16)+kt)*N + n)*16 + tig*4 + e,  k = 16kt+tig+4e)
struct TSeg { const float* src; float* dst; int K; int N; int total; };
struct TArgs { TSeg seg[9]; };
__global__ void prep_weights(TArgs a) {
    int s = blockIdx.y;
    int i = blockIdx.x * 256 + threadIdx.x;
    TSeg sg = a.seg[s];
    if (i >= sg.total) return;
    int KN = sg.K * sg.N;
    int d = i / KN, r = i % KN;
    int k = r / sg.N, n = r % sg.N;
    int kt = k >> 4, kr = k & 15;
    int tig = kr & 3, e = kr >> 2;
    size_t dst = ((size_t)(d * (sg.K >> 4) + kt) * sg.N + n) * 16 + tig * 4 + e;
    sg.dst[dst] = roundtf(sg.src[i]);
}

// ------------------------- embedding gather (+ zero sums) ---------------
__global__ void embed_kernel(const int* __restrict__ id_idx,
                             const int* __restrict__ agn_idx,
                             const float* __restrict__ id_tab,
                             const float* __restrict__ agn_tab) {
    int t = blockIdx.x * blockDim.x + threadIdx.x;
    if (t < 3 * 2 * DNUM * 256) ((float*)g_sums3)[t] = 0.0f;
    if (t >= BSZ * 64) return;
    int b = t >> 6;
    int j = (t & 63) << 2;
    const int*   idx = id_idx;
    const float* tab = id_tab;
    int jj = j;
    if (j >= 128) { idx = agn_idx; tab = agn_tab; jj = j - 128; }
    int f = jj >> 4, e = jj & 15;
    int v = idx[b * NFEAT + f];
    float4 val = *(const float4*)(tab + ((size_t)f * VOCAB + v) * EDIM + e);
    val.x = roundtf(val.x); val.y = roundtf(val.y);
    val.z = roundtf(val.z); val.w = roundtf(val.w);
    *(float4*)(g_gate_in + (size_t)b * IND + j) = val;
}

// ------------------------- tensor-core GEMM ------------------------------
// C[d] = A[d] (BSZ x K, tf32-rounded) @ W(packed)[d] + bias[d]
// EPI: 0 = none + column stats, 1 = relu+round, 2 = 2*sigmoid
// BM=128, BK=16. 8 warps (4m x 2n). Warp tile 32 x (BN/2).
template <int BN, int EPI>
__global__ void __launch_bounds__(256, 2)
gemm_tc(const float* __restrict__ A, size_t aDomStride,
        const float* __restrict__ Wp,
        const float* __restrict__ bias,
        float* __restrict__ C,
        float* __restrict__ sums,
        int K, int N) {
    constexpr int BM = 128, BK = 16;
    constexpr int WN = BN / 2;
    constexpr int NI = WN / 8;               // 8 or 4
    constexpr int APAD = 20;
    constexpr int BQ = BN * 4;               // float4 quads per B chunk

    __shared__ __align__(16) float As[2][BM][APAD];
    __shared__ __align__(16) float Bs[2][BN * 16];
    __shared__ float cs[BN], cq[BN];

    int d  = blockIdx.z;
    int bm = blockIdx.x * BM;
    int bn = blockIdx.y * BN;
    const float* Ad = A + (size_t)d * aDomStride + (size_t)bm * K;
    // packed weights: d-base + bn offset (16 floats per column)
    const float* Bd = Wp + (size_t)d * K * N + (size_t)bn * 16;
    float*       Cd = C + ((size_t)d * BSZ + bm) * N + bn;

    int tid  = threadIdx.x;
    int lane = tid & 31, wid = tid >> 5;
    int gid  = lane >> 2, tig = lane & 3;
    int wm   = wid >> 1,  wn  = wid & 1;

    int arow = tid >> 2, akc = (tid & 3) << 2;     // A: 64 rows x 16k, two row groups

    const float* Aptr0 = Ad + (size_t)arow * K + akc;
    const float* Aptr1 = Ad + (size_t)(arow + 64) * K + akc;

    uint32_t sA = (uint32_t)__cvta_generic_to_shared(&As[0][0][0]);
    uint32_t sB = (uint32_t)__cvta_generic_to_shared(&Bs[0][0]);

    float acc[2][NI][4] = {};

    // stage chunk (kt) into buffer st
    auto stage = [&](int kt, int st) {
        cp16(sA + (((st * BM + arow) * APAD + akc) << 2), Aptr0 + kt * 16);
        cp16(sA + (((st * BM + arow + 64) * APAD + akc) << 2), Aptr1 + kt * 16);
        const float* Bq = Bd + (size_t)kt * N * 16;
#pragma unroll
        for (int i = 0; i < BQ / 256; i++) {
            int q = tid + i * 256;
            cp16(sB + ((st * BN * 16 + q * 4) << 2), Bq + q * 4);
        }
        CP_COMMIT();
    };

    const int NCH = K / BK;
    stage(0, 0);

    int s = 0;
    for (int c = 0; c < NCH; c++) {
        CP_WAIT0();
        __syncthreads();

        if (c + 1 < NCH) stage(c + 1, s ^ 1);

        // load all B fragments for this k-tile: one LDS.128 per ni
        float4 bq[NI];
#pragma unroll
        for (int ni = 0; ni < NI; ni++) {
            int cb = wn * WN + ni * 8 + gid;
            bq[ni] = *(const float4*)&Bs[s][cb * 16 + tig * 4];
        }

#pragma unroll
        for (int ks = 0; ks < 2; ks++) {
            int kk = ks * 8;
            unsigned af[2][4];
#pragma unroll
            for (int mi = 0; mi < 2; mi++) {
                int r0 = wm * 32 + mi * 16 + gid;
                af[mi][0] = __float_as_uint(As[s][r0][kk + tig]);
                af[mi][1] = __float_as_uint(As[s][r0 + 8][kk + tig]);
                af[mi][2] = __float_as_uint(As[s][r0][kk + tig + 4]);
                af[mi][3] = __float_as_uint(As[s][r0 + 8][kk + tig + 4]);
            }
#pragma unroll
            for (int mi = 0; mi < 2; mi++)
#pragma unroll
                for (int ni = 0; ni < NI; ni++) {
                    unsigned b2[2];
                    if (ks == 0) { b2[0] = __float_as_uint(bq[ni].x); b2[1] = __float_as_uint(bq[ni].y); }
                    else         { b2[0] = __float_as_uint(bq[ni].z); b2[1] = __float_as_uint(bq[ni].w); }
                    mma_tf32(acc[mi][ni], af[mi], b2);
                }
        }
        s ^= 1;
    }

    if (EPI == 0) {
        if (tid < BN) { cs[tid] = 0.0f; cq[tid] = 0.0f; }
        __syncthreads();
    }

    float colS[NI][2] = {}, colQ[NI][2] = {};

#pragma unroll
    for (int mi = 0; mi < 2; mi++) {
        int r0 = wm * 32 + mi * 16 + gid;
#pragma unroll
        for (int ni = 0; ni < NI; ni++) {
            int col = wn * WN + ni * 8 + 2 * tig;
            float b0 = bias[d * N + bn + col];
            float b1 = bias[d * N + bn + col + 1];
            float v0 = acc[mi][ni][0] + b0;
            float v1 = acc[mi][ni][1] + b1;
            float v2 = acc[mi][ni][2] + b0;
            float v3 = acc[mi][ni][3] + b1;
            if (EPI == 1) {
                v0 = roundtf(fmaxf(v0, 0.0f)); v1 = roundtf(fmaxf(v1, 0.0f));
                v2 = roundtf(fmaxf(v2, 0.0f)); v3 = roundtf(fmaxf(v3, 0.0f));
            }
            if (EPI == 2) {
                v0 = 2.0f / (1.0f + expf(-v0)); v1 = 2.0f / (1.0f + expf(-v1));
                v2 = 2.0f / (1.0f + expf(-v2)); v3 = 2.0f / (1.0f + expf(-v3));
            }
            if (EPI == 0) {
                colS[ni][0] += v0 + v2;      colS[ni][1] += v1 + v3;
                colQ[ni][0] += v0 * v0 + v2 * v2;
                colQ[ni][1] += v1 * v1 + v3 * v3;
            }
            *(float2*)(Cd + (size_t)r0 * N + col)       = make_float2(v0, v1);
            *(float2*)(Cd + (size_t)(r0 + 8) * N + col) = make_float2(v2, v3);
        }
    }

    if (EPI == 0) {
#pragma unroll
        for (int ni = 0; ni < NI; ni++)
#pragma unroll
            for (int c2 = 0; c2 < 2; c2++) {
                float sv = colS[ni][c2], qv = colQ[ni][c2];
                sv += __shfl_xor_sync(0xffffffffu, sv, 16);
                sv += __shfl_xor_sync(0xffffffffu, sv, 8);
                sv += __shfl_xor_sync(0xffffffffu, sv, 4);
                qv += __shfl_xor_sync(0xffffffffu, qv, 16);
                qv += __shfl_xor_sync(0xffffffffu, qv, 8);
                qv += __shfl_xor_sync(0xffffffffu, qv, 4);
                if (gid == 0) {
                    int c = wn * WN + ni * 8 + 2 * tig + c2;
                    atomicAdd(&cs[c], sv);
                    atomicAdd(&cq[c], qv);
                }
            }
        __syncthreads();
        if (tid < BN) {
            atomicAdd(&sums[d * 256 + bn + tid], cs[tid]);
            atomicAdd(&sums[DNUM * 256 + d * 256 + bn + tid], cq[tid]);
        }
    }
}

// ------------------------- BN apply + gate ------------------------------
__global__ void bn_apply_gate(float* __restrict__ H, const float* __restrict__ G,
                              const float* __restrict__ sums,
                              const float* __restrict__ bng,
                              const float* __restrict__ bnb, int N) {
    size_t t = (size_t)blockIdx.x * blockDim.x + threadIdx.x;
    size_t total4 = (size_t)DNUM * BSZ * N / 4;
    if (t >= total4) return;
    size_t e = t * 4;
    int c = (int)(e % N);
    int d = (int)(e / ((size_t)BSZ * N));
    float4 h = *(float4*)(H + e);
    float4 g = *(const float4*)(G + e);
    float r[4] = {h.x, h.y, h.z, h.w};
    float gg[4] = {g.x, g.y, g.z, g.w};
#pragma unroll
    for (int j = 0; j < 4; j++) {
        int idx = d * 256 + c + j;
        float mean = sums[idx] * (1.0f / BSZ);
        float var  = sums[DNUM * 256 + idx] * (1.0f / BSZ) - mean * mean;
        float sc   = bng[d * N + c + j] * rsqrtf(var + 1e-5f);
        float sh   = bnb[d * N + c + j] - mean * sc;
        r[j] = roundtf(fmaxf(r[j] * sc + sh, 0.0f) * gg[j]);
    }
    *(float4*)(H + e) = make_float4(r[0], r[1], r[2], r[3]);
}

// ------------------------- final head -----------------------------------
__global__ void final_kernel(const float* __restrict__ H,
                             const int* __restrict__ dom,
                             const float* __restrict__ finW,
                             const float* __restrict__ finb,
                             float* __restrict__ out) {
    int warp = (blockIdx.x * blockDim.x + threadIdx.x) >> 5;
    int lane = threadIdx.x & 31;
    if (warp >= BSZ) return;
    int d = dom[warp];
    const float* h = H + ((size_t)d * BSZ + warp) * 64;
    const float* w = finW + d * 64;
    float s = h[lane] * w[lane] + h[lane + 32] * w[lane + 32];
#pragma unroll
    for (int o = 16; o > 0; o >>= 1) s += __shfl_down_sync(0xffffffffu, s, o);
    if (lane == 0) out[warp] = 1.0f / (1.0f + expf(-(s + finb[d])));
}

// ------------------------- dispatch helper ------------------------------
template <int EPI>
static void launch_gemm(const float* A, size_t aStride, const float* Wp,
                        const float* b, float* C, float* sums, int K, int N) {
    if (N >= 128) {
        dim3 grid(BSZ / 128, N / 128, DNUM);
        gemm_tc<128, EPI><<<grid, 256>>>(A, aStride, Wp, b, C, sums, K, N);
    } else {
        dim3 grid(BSZ / 128, N / 64, DNUM);
        gemm_tc<64, EPI><<<grid, 256>>>(A, aStride, Wp, b, C, sums, K, N);
    }
}

// ------------------------- launch --------------------------------------
extern "C" void kernel_launch(void* const* d_in, const int* in_sizes, int n_in,
                              void* d_out, int out_size) {
    const int*   id_idx    = (const int*)d_in[0];
    const int*   agn_idx   = (const int*)d_in[1];
    const int*   domain_id = (const int*)d_in[2];
    const float* id_tab    = (const float*)d_in[3];
    const float* agn_tab   = (const float*)d_in[4];
    const float* mlp_W[3]  = {(const float*)d_in[5],  (const float*)d_in[13], (const float*)d_in[21]};
    const float* mlp_b[3]  = {(const float*)d_in[6],  (const float*)d_in[14], (const float*)d_in[22]};
    const float* bn_g[3]   = {(const float*)d_in[7],  (const float*)d_in[15], (const float*)d_in[23]};
    const float* bn_b[3]   = {(const float*)d_in[8],  (const float*)d_in[16], (const float*)d_in[24]};
    const float* gW1[3]    = {(const float*)d_in[9],  (const float*)d_in[17], (const float*)d_in[25]};
    const float* gb1[3]    = {(const float*)d_in[10], (const float*)d_in[18], (const float*)d_in[26]};
    const float* gW2[3]    = {(const float*)d_in[11], (const float*)d_in[19], (const float*)d_in[27]};
    const float* gb2[3]    = {(const float*)d_in[12], (const float*)d_in[20], (const float*)d_in[28]};
    const float* finW      = (const float*)d_in[29];
    const float* finb      = (const float*)d_in[30];
    float*       out       = (float*)d_out;

    float *p_gate_in, *p_h0, *p_h1, *p_g1, *p_gt, *p_sums, *p_w;
    cudaGetSymbolAddress((void**)&p_gate_in, g_gate_in);
    cudaGetSymbolAddress((void**)&p_h0, g_h0);
    cudaGetSymbolAddress((void**)&p_h1, g_h1);
    cudaGetSymbolAddress((void**)&p_g1, g_g1);
    cudaGetSymbolAddress((void**)&p_gt, g_gt);
    cudaGetSymbolAddress((void**)&p_sums, g_sums3);
    cudaGetSymbolAddress((void**)&p_w, g_wrnd);

    const int dims[4] = {256, 256, 128, 64};

    // packed weights
    float* rW1[3]; float* rW2[3]; float* rWm[3];
    size_t off = 0;
    TArgs ta;
    int segi = 0, maxn = 0;
    for (int i = 0; i < 3; i++) {
        int N = dims[i + 1];
        rW1[i] = p_w + off;
        ta.seg[segi++] = {gW1[i], p_w + off, IND, N, DNUM * IND * N};           off += (size_t)DNUM * IND * N;
        rW2[i] = p_w + off;
        ta.seg[segi++] = {gW2[i], p_w + off, N, N, DNUM * N * N};               off += (size_t)DNUM * N * N;
        rWm[i] = p_w + off;
        ta.seg[segi++] = {mlp_W[i], p_w + off, dims[i], N, DNUM * dims[i] * N}; off += (size_t)DNUM * dims[i] * N;
    }
    for (int s = 0; s < 9; s++) if (ta.seg[s].total > maxn) maxn = ta.seg[s].total;

    dim3 rg((maxn + 255) / 256, 9);
    prep_weights<<<rg, 256>>>(ta);

    embed_kernel<<<(BSZ * 64 + 255) / 256, 256>>>(id_idx, agn_idx, id_tab, agn_tab);

    float* hbuf[2] = {p_h0, p_h1};
    const float* hprev = nullptr;

    for (int i = 0; i < 3; i++) {
        int Kmlp = dims[i];
        int N    = dims[i + 1];
        float* hout = hbuf[i & 1];
        float* sums = p_sums + (size_t)i * 2 * DNUM * 256;

        launch_gemm<1>(p_gate_in, 0, rW1[i], gb1[i], p_g1, nullptr, IND, N);
        launch_gemm<2>(p_g1, (size_t)BSZ * N, rW2[i], gb2[i], p_gt, nullptr, N, N);
        if (i == 0)
            launch_gemm<0>(p_gate_in, 0, rWm[i], mlp_b[i], hout, sums, IND, N);
        else
            launch_gemm<0>(hprev, (size_t)BSZ * Kmlp, rWm[i], mlp_b[i], hout, sums, Kmlp, N);

        size_t tot4 = (size_t)DNUM * BSZ * N / 4;
        bn_apply_gate<<<(unsigned)((tot4 + 255) / 256), 256>>>(hout, p_gt, sums, bn_g[i], bn_b[i], N);

        hprev = hout;
    }

    final_kernel<<<BSZ / 8, 256>>>(hprev, domain_id, finW, finb, out);
}